// round 1
// baseline (speedup 1.0000x reference)
#include <cuda_runtime.h>

#define BATCH 32768
#define IN1   784
#define HID   256
#define OUT   10
#define W1B   98    // packed int32 per hidden row (bytes, one per int)
#define W2B   32    // packed int32 per output row

// Scratch (allocation-free rule: __device__ globals)
__device__ float g_w1f[HID * IN1];    // [256][784]
__device__ float g_w2f[OUT * HID];    // [10][256]
__device__ float g_h[(size_t)BATCH * HID];  // [32768][256]

// ---------------------------------------------------------------------------
// Unpack: bit i of row o lives in byte i>>3, MSB-first (shift 7-(i&7)).
// w = (2*bit-1) * maskbit * alpha
// ---------------------------------------------------------------------------
__global__ void unpack_w1(const int* __restrict__ wp, const int* __restrict__ mp,
                          const float* __restrict__ alpha) {
    int idx = blockIdx.x * blockDim.x + threadIdx.x;
    if (idx >= HID * IN1) return;
    int o = idx / IN1, i = idx - o * IN1;
    int sh = 7 - (i & 7);
    int wb = (wp[o * W1B + (i >> 3)] >> sh) & 1;
    int mb = (mp[o * W1B + (i >> 3)] >> sh) & 1;
    g_w1f[idx] = (2.0f * (float)wb - 1.0f) * (float)mb * alpha[0];
}

__global__ void unpack_w2(const int* __restrict__ wp, const int* __restrict__ mp,
                          const float* __restrict__ alpha) {
    int idx = blockIdx.x * blockDim.x + threadIdx.x;
    if (idx >= OUT * HID) return;
    int o = idx / HID, i = idx - o * HID;
    int sh = 7 - (i & 7);
    int wb = (wp[o * W2B + (i >> 3)] >> sh) & 1;
    int mb = (mp[o * W2B + (i >> 3)] >> sh) & 1;
    g_w2f[idx] = (2.0f * (float)wb - 1.0f) * (float)mb * alpha[0];
}

// ---------------------------------------------------------------------------
// GEMM1: h[b,o] = relu( sum_i x[b,i] * w1[o,i] )   (NT gemm)
// Block tile 128(M=batch) x 64(N=hidden), BK=16, 128 threads, 8x8 microtile.
// ---------------------------------------------------------------------------
#define BM 128
#define BN 64
#define BK 16

__global__ void __launch_bounds__(128) gemm1(const float* __restrict__ x) {
    __shared__ __align__(16) float As[BK][BM + 4];   // +4 pad: row stride 132 (16B-aligned)
    __shared__ __align__(16) float Bs[BK][BN + 4];   // row stride 68 (16B-aligned)

    const int tid = threadIdx.x;
    const int tx = tid & 7;        // 0..7  -> N
    const int ty = tid >> 3;       // 0..15 -> M
    const int bm = blockIdx.y * BM;
    const int bn = blockIdx.x * BN;

    const float* __restrict__ xblk = x + (size_t)bm * IN1;
    const float* __restrict__ wblk = g_w1f + (size_t)bn * IN1;

    float acc[8][8];
    #pragma unroll
    for (int m = 0; m < 8; m++)
        #pragma unroll
        for (int n = 0; n < 8; n++) acc[m][n] = 0.0f;

    for (int kt = 0; kt < IN1; kt += BK) {
        // A tile: 128 rows x 16 cols = 512 float4, 4 per thread (transposed store)
        #pragma unroll
        for (int r = 0; r < 4; r++) {
            int idx = tid + r * 128;           // 0..511
            int row = idx >> 2, c4 = idx & 3;
            float4 v = *(const float4*)(xblk + (size_t)row * IN1 + kt + c4 * 4);
            As[c4 * 4 + 0][row] = v.x;
            As[c4 * 4 + 1][row] = v.y;
            As[c4 * 4 + 2][row] = v.z;
            As[c4 * 4 + 3][row] = v.w;
        }
        // B tile: 64 rows x 16 cols = 256 float4, 2 per thread
        #pragma unroll
        for (int r = 0; r < 2; r++) {
            int idx = tid + r * 128;           // 0..255
            int row = idx >> 2, c4 = idx & 3;
            float4 v = *(const float4*)(wblk + (size_t)row * IN1 + kt + c4 * 4);
            Bs[c4 * 4 + 0][row] = v.x;
            Bs[c4 * 4 + 1][row] = v.y;
            Bs[c4 * 4 + 2][row] = v.z;
            Bs[c4 * 4 + 3][row] = v.w;
        }
        __syncthreads();

        #pragma unroll
        for (int k = 0; k < BK; k++) {
            float a[8], b[8];
            *(float4*)&a[0] = *(const float4*)&As[k][ty * 8];
            *(float4*)&a[4] = *(const float4*)&As[k][ty * 8 + 4];
            *(float4*)&b[0] = *(const float4*)&Bs[k][tx * 8];
            *(float4*)&b[4] = *(const float4*)&Bs[k][tx * 8 + 4];
            #pragma unroll
            for (int m = 0; m < 8; m++)
                #pragma unroll
                for (int n = 0; n < 8; n++)
                    acc[m][n] = fmaf(a[m], b[n], acc[m][n]);
        }
        __syncthreads();
    }

    // ReLU + store h
    #pragma unroll
    for (int m = 0; m < 8; m++) {
        int row = bm + ty * 8 + m;
        float* hp = g_h + (size_t)row * HID + bn + tx * 8;
        float4 v0, v1;
        v0.x = fmaxf(acc[m][0], 0.f); v0.y = fmaxf(acc[m][1], 0.f);
        v0.z = fmaxf(acc[m][2], 0.f); v0.w = fmaxf(acc[m][3], 0.f);
        v1.x = fmaxf(acc[m][4], 0.f); v1.y = fmaxf(acc[m][5], 0.f);
        v1.z = fmaxf(acc[m][6], 0.f); v1.w = fmaxf(acc[m][7], 0.f);
        *(float4*)(hp)     = v0;
        *(float4*)(hp + 4) = v1;
    }
}

// ---------------------------------------------------------------------------
// Layer 2: out[b,o] = sum_h h[b,h] * w2[o,h].  One warp per batch row.
// ---------------------------------------------------------------------------
__global__ void __launch_bounds__(256) layer2(float* __restrict__ out) {
    __shared__ float w2s[OUT * HID];
    int tid = threadIdx.x;
    for (int i = tid; i < OUT * HID; i += 256) w2s[i] = g_w2f[i];
    __syncthreads();

    int warp = tid >> 5, lane = tid & 31;
    int b = blockIdx.x * 8 + warp;

    const float4* __restrict__ hrow = (const float4*)(g_h + (size_t)b * HID);
    float acc[OUT];
    #pragma unroll
    for (int o = 0; o < OUT; o++) acc[o] = 0.0f;

    #pragma unroll
    for (int j = 0; j < 2; j++) {
        int q = lane + 32 * j;          // float4 index within the 256-wide row
        float4 hv = hrow[q];
        int hb = q * 4;
        #pragma unroll
        for (int o = 0; o < OUT; o++) {
            const float* w = &w2s[o * HID + hb];
            acc[o] = fmaf(hv.x, w[0], acc[o]);
            acc[o] = fmaf(hv.y, w[1], acc[o]);
            acc[o] = fmaf(hv.z, w[2], acc[o]);
            acc[o] = fmaf(hv.w, w[3], acc[o]);
        }
    }

    #pragma unroll
    for (int o = 0; o < OUT; o++) {
        float v = acc[o];
        #pragma unroll
        for (int s = 16; s > 0; s >>= 1)
            v += __shfl_xor_sync(0xffffffffu, v, s);
        if (lane == o) out[(size_t)b * OUT + o] = v;
    }
}

// ---------------------------------------------------------------------------
extern "C" void kernel_launch(void* const* d_in, const int* in_sizes, int n_in,
                              void* d_out, int out_size) {
    const float* x   = (const float*)d_in[0];
    const int*   w1p = (const int*)d_in[1];
    const int*   m1p = (const int*)d_in[2];
    const float* a1  = (const float*)d_in[3];
    const int*   w2p = (const int*)d_in[4];
    const int*   m2p = (const int*)d_in[5];
    const float* a2  = (const float*)d_in[6];
    float* out = (float*)d_out;

    unpack_w1<<<(HID * IN1 + 255) / 256, 256>>>(w1p, m1p, a1);
    unpack_w2<<<(OUT * HID + 255) / 256, 256>>>(w2p, m2p, a2);
    gemm1<<<dim3(HID / BN, BATCH / BM), 128>>>(x);
    layer2<<<BATCH / 8, 256>>>(out);
}

// round 3
// speedup vs baseline: 3.5476x; 3.5476x over previous
#include <cuda_runtime.h>
#include <cuda_bf16.h>
#include <cstdint>

#define BATCH 32768
#define IN1   784
#define KPAD  832          // 13 * 64
#define HID   256
#define OUT   10
#define W1B   98
#define W2B   32
#define KC    64
#define NCHUNK 13
#define BM    128
#define NTHR  256

// -------- device scratch (allocation-free rule) --------
__device__ __align__(16) __nv_bfloat16 g_w1bf[HID * KPAD];  // [256][832] bf16 {-1,0,+1}
__device__ float g_w2f[OUT * HID];                          // [10][256] fp32 (incl alpha2)

// -------- shared memory layout (bytes) --------
#define SM_AHI  0                      // 128 x 64 bf16 = 16KB
#define SM_ALO  16384                  // 16KB
#define SM_B(s) (32768 + (s) * 32768)  // 256 x 64 bf16 = 32KB x2
#define SM_W2   98304                  // 10KB
#define SM_PART 0                      // epilogue alias: 4 x 128 x 10 fp32 = 20KB
#define SMEM_TOTAL (98304 + OUT * HID * 4)

// -------- helpers --------
__device__ __forceinline__ uint32_t smem_u32(const void* p) {
    uint32_t a;
    asm("{ .reg .u64 t; cvta.to.shared.u64 t, %1; cvt.u32.u64 %0, t; }" : "=r"(a) : "l"(p));
    return a;
}
__device__ __forceinline__ uint32_t swz(uint32_t off) {  // SW128: bits[6:4] ^= bits[9:7]
    return off ^ ((off >> 3) & 0x70);
}
__device__ __forceinline__ uint32_t pk(__nv_bfloat16 a, __nv_bfloat16 b) {
    __nv_bfloat162 t(a, b);
    return *reinterpret_cast<uint32_t*>(&t);
}
__device__ __forceinline__ void ldm_x4(uint32_t& r0, uint32_t& r1, uint32_t& r2, uint32_t& r3,
                                       uint32_t addr) {
    asm volatile("ldmatrix.sync.aligned.m8n8.x4.shared.b16 {%0,%1,%2,%3}, [%4];"
                 : "=r"(r0), "=r"(r1), "=r"(r2), "=r"(r3) : "r"(addr));
}
__device__ __forceinline__ void mma16816(float* d, const uint32_t* a, const uint32_t* b) {
    asm volatile(
        "mma.sync.aligned.m16n8k16.row.col.f32.bf16.bf16.f32 "
        "{%0,%1,%2,%3}, {%4,%5,%6,%7}, {%8,%9}, {%0,%1,%2,%3};"
        : "+f"(d[0]), "+f"(d[1]), "+f"(d[2]), "+f"(d[3])
        : "r"(a[0]), "r"(a[1]), "r"(a[2]), "r"(a[3]), "r"(b[0]), "r"(b[1]));
}
__device__ __forceinline__ void cpa16(uint32_t dst, const void* src) {
    asm volatile("cp.async.cg.shared.global [%0], [%1], 16;" :: "r"(dst), "l"(src) : "memory");
}

// ---------------------------------------------------------------------------
// Unpack: w1 -> bf16 {-1,0,+1} padded K to 832; w2 -> fp32 * alpha2.
// ---------------------------------------------------------------------------
__global__ void unpack_all(const int* __restrict__ w1p, const int* __restrict__ m1p,
                           const int* __restrict__ w2p, const int* __restrict__ m2p,
                           const float* __restrict__ a2) {
    int idx = blockIdx.x * 256 + threadIdx.x;
    if (idx < HID * KPAD) {
        int o = idx / KPAD, i = idx - o * KPAD;
        float v = 0.0f;
        if (i < IN1) {
            int sh = 7 - (i & 7);
            int wb = (w1p[o * W1B + (i >> 3)] >> sh) & 1;
            int mb = (m1p[o * W1B + (i >> 3)] >> sh) & 1;
            v = (2.0f * (float)wb - 1.0f) * (float)mb;
        }
        g_w1bf[idx] = __float2bfloat16(v);
    } else {
        int j = idx - HID * KPAD;
        if (j < OUT * HID) {
            int o = j / HID, i = j - o * HID;
            int sh = 7 - (i & 7);
            int wb = (w2p[o * W2B + (i >> 3)] >> sh) & 1;
            int mb = (m2p[o * W2B + (i >> 3)] >> sh) & 1;
            g_w2f[j] = (2.0f * (float)wb - 1.0f) * (float)mb * a2[0];
        }
    }
}

// ---------------------------------------------------------------------------
// Fused: D[128,256] = x_tile @ w1^T via mma.sync bf16 (hi+lo split, fp32 acc),
// epilogue: out = relu(alpha1*D) @ w2^T.
// ---------------------------------------------------------------------------
__global__ void __launch_bounds__(NTHR, 1)
fused(const float* __restrict__ x, const float* __restrict__ alpha1,
      float* __restrict__ out) {
    extern __shared__ char smem[];
    const uint32_t sb = smem_u32(smem);
    const int tid = threadIdx.x, wid = tid >> 5, lane = tid & 31;
    const int wm = wid >> 2, wn = wid & 3;        // 2 x 4 warp grid, 64x64 tiles
    const int bm = blockIdx.x * BM;
    const float* __restrict__ xb = x + (size_t)bm * IN1;

    // stage w2 (epilogue operand)
    for (int i = tid; i < OUT * HID; i += NTHR)
        reinterpret_cast<float*>(smem + SM_W2)[i] = g_w2f[i];

    float acc[4][8][4];
    #pragma unroll
    for (int i = 0; i < 4; ++i)
        #pragma unroll
        for (int j = 0; j < 8; ++j)
            #pragma unroll
            for (int r = 0; r < 4; ++r) acc[i][j][r] = 0.0f;

    float4 sa[8];                                  // x staging regs
    const int g = lane >> 3, lr = lane & 7;        // ldmatrix lane grouping

    auto loadA = [&](int c) {
        const int kt = c * KC;
        #pragma unroll
        for (int it = 0; it < 8; ++it) {
            int idx = tid + it * NTHR;             // 0..2047 float4 slots
            int row = idx >> 4, f = idx & 15;
            int col = kt + f * 4;
            if (col < IN1)
                sa[it] = *reinterpret_cast<const float4*>(xb + (size_t)row * IN1 + col);
            else
                sa[it] = make_float4(0.f, 0.f, 0.f, 0.f);
        }
    };
    auto storeA = [&]() {
        #pragma unroll
        for (int it = 0; it < 8; ++it) {
            int idx = tid + it * NTHR;
            int row = idx >> 4, f = idx & 15;
            float4 v = sa[it];
            __nv_bfloat16 hx = __float2bfloat16(v.x), hy = __float2bfloat16(v.y);
            __nv_bfloat16 hz = __float2bfloat16(v.z), hw = __float2bfloat16(v.w);
            __nv_bfloat16 lx = __float2bfloat16(v.x - __bfloat162float(hx));
            __nv_bfloat16 ly = __float2bfloat16(v.y - __bfloat162float(hy));
            __nv_bfloat16 lz = __float2bfloat16(v.z - __bfloat162float(hz));
            __nv_bfloat16 lw = __float2bfloat16(v.w - __bfloat162float(hw));
            uint32_t sw = swz((uint32_t)(row * 128 + f * 8));
            *reinterpret_cast<uint2*>(smem + SM_AHI + sw) = make_uint2(pk(hx, hy), pk(hz, hw));
            *reinterpret_cast<uint2*>(smem + SM_ALO + sw) = make_uint2(pk(lx, ly), pk(lz, lw));
        }
    };
    auto issueB = [&](int c, int s) {
        const int kt = c * KC;
        #pragma unroll
        for (int it = 0; it < 8; ++it) {
            int idx = tid + it * NTHR;             // 0..2047 16B granules
            int n = idx >> 3, u = idx & 7;
            cpa16(sb + SM_B(s) + swz((uint32_t)(n * 128 + u * 16)),
                  g_w1bf + (size_t)n * KPAD + kt + u * 8);
        }
        asm volatile("cp.async.commit_group;" ::: "memory");
    };
    auto compute = [&](int s) {
        #pragma unroll
        for (int ks = 0; ks < 4; ++ks) {
            uint32_t b[8][2];
            #pragma unroll
            for (int p = 0; p < 4; ++p) {
                int n  = wn * 64 + p * 16 + ((g & 2) ? 8 : 0) + lr;
                int kk = ks * 16 + ((g & 1) ? 8 : 0);
                ldm_x4(b[2 * p][0], b[2 * p][1], b[2 * p + 1][0], b[2 * p + 1][1],
                       sb + SM_B(s) + swz((uint32_t)(n * 128 + kk * 2)));
            }
            uint32_t a[4][4];
            #pragma unroll
            for (int i = 0; i < 4; ++i) {
                int row = wm * 64 + i * 16 + ((g & 1) ? 8 : 0) + lr;
                int kk  = ks * 16 + ((g & 2) ? 8 : 0);
                ldm_x4(a[i][0], a[i][1], a[i][2], a[i][3],
                       sb + SM_AHI + swz((uint32_t)(row * 128 + kk * 2)));
            }
            #pragma unroll
            for (int i = 0; i < 4; ++i)
                #pragma unroll
                for (int j = 0; j < 8; ++j) mma16816(acc[i][j], a[i], b[j]);
            #pragma unroll
            for (int i = 0; i < 4; ++i) {
                int row = wm * 64 + i * 16 + ((g & 1) ? 8 : 0) + lr;
                int kk  = ks * 16 + ((g & 2) ? 8 : 0);
                ldm_x4(a[i][0], a[i][1], a[i][2], a[i][3],
                       sb + SM_ALO + swz((uint32_t)(row * 128 + kk * 2)));
            }
            #pragma unroll
            for (int i = 0; i < 4; ++i)
                #pragma unroll
                for (int j = 0; j < 8; ++j) mma16816(acc[i][j], a[i], b[j]);
        }
    };

    // ---- prologue ----
    issueB(0, 0);
    loadA(0);
    storeA();
    issueB(1, 1);
    loadA(1);
    asm volatile("cp.async.wait_group 1;" ::: "memory");
    __syncthreads();

    // ---- mainloop ----
    for (int c = 0; c < NCHUNK; ++c) {
        compute(c & 1);
        if (c < NCHUNK - 1) {
            __syncthreads();
            storeA();                               // A tile for chunk c+1
            if (c < NCHUNK - 2) {
                issueB(c + 2, c & 1);
                loadA(c + 2);
                asm volatile("cp.async.wait_group 1;" ::: "memory");
            } else {
                asm volatile("cp.async.wait_group 0;" ::: "memory");
            }
            __syncthreads();
        }
    }

    // ---- epilogue: out = relu(a1*acc) @ w2^T ----
    __syncthreads();                                // before aliasing tile smem
    const float a1v = alpha1[0];
    #pragma unroll
    for (int i = 0; i < 4; ++i)
        #pragma unroll
        for (int j = 0; j < 8; ++j)
            #pragma unroll
            for (int r = 0; r < 4; ++r)
                acc[i][j][r] = fmaxf(a1v * acc[i][j][r], 0.0f);

    const float* w2s = reinterpret_cast<const float*>(smem + SM_W2);
    float* part = reinterpret_cast<float*>(smem + SM_PART);
    const int q = lane & 3, gq = lane >> 2;

    #pragma unroll
    for (int o = 0; o < OUT; ++o) {
        float w2v[8][2];
        #pragma unroll
        for (int j = 0; j < 8; ++j) {
            w2v[j][0] = w2s[o * HID + wn * 64 + j * 8 + q * 2];
            w2v[j][1] = w2s[o * HID + wn * 64 + j * 8 + q * 2 + 1];
        }
        #pragma unroll
        for (int i = 0; i < 4; ++i)
            #pragma unroll
            for (int h2 = 0; h2 < 2; ++h2) {
                float s = 0.0f;
                #pragma unroll
                for (int j = 0; j < 8; ++j)
                    s += acc[i][j][h2 * 2] * w2v[j][0] + acc[i][j][h2 * 2 + 1] * w2v[j][1];
                s += __shfl_xor_sync(0xffffffffu, s, 1);
                s += __shfl_xor_sync(0xffffffffu, s, 2);
                if (q == 0) {
                    int row = wm * 64 + i * 16 + h2 * 8 + gq;
                    part[wn * (BM * OUT) + row * OUT + o] = s;
                }
            }
    }
    __syncthreads();

    for (int idx = tid; idx < BM * OUT; idx += NTHR) {
        float v = part[idx] + part[BM * OUT + idx] +
                  part[2 * BM * OUT + idx] + part[3 * BM * OUT + idx];
        out[(size_t)bm * OUT + idx] = v;
    }
}

// ---------------------------------------------------------------------------
extern "C" void kernel_launch(void* const* d_in, const int* in_sizes, int n_in,
                              void* d_out, int out_size) {
    const float* x   = (const float*)d_in[0];
    const int*   w1p = (const int*)d_in[1];
    const int*   m1p = (const int*)d_in[2];
    const float* a1  = (const float*)d_in[3];
    const int*   w2p = (const int*)d_in[4];
    const int*   m2p = (const int*)d_in[5];
    const float* a2  = (const float*)d_in[6];
    float* out = (float*)d_out;

    cudaFuncSetAttribute(fused, cudaFuncAttributeMaxDynamicSharedMemorySize, SMEM_TOTAL);

    int total = HID * KPAD + OUT * HID;
    unpack_all<<<(total + 255) / 256, 256>>>(w1p, m1p, w2p, m2p, a2);
    fused<<<BATCH / BM, NTHR, SMEM_TOTAL>>>(x, a1, out);
}

// round 4
// speedup vs baseline: 5.4902x; 1.5476x over previous
#include <cuda_runtime.h>
#include <cuda_fp16.h>
#include <cstdint>

#define BATCH 32768
#define IN1   784
#define KPAD  832          // 13 * 64
#define HID   256
#define OUT   10
#define W1B   98
#define W2B   32
#define KC    64
#define NCHUNK 13
#define BM    128
#define NTHR  256

// -------- device scratch (allocation-free rule) --------
__device__ __align__(16) __half g_w1h[HID * KPAD];   // [256][832] fp16 {-1,0,+1}
__device__ float g_w2f[OUT * HID];                   // [10][256] fp32 (incl alpha2)

// -------- shared memory layout (bytes) --------
#define SM_A(s) ((s) * 16384)              // 128 x 64 fp16 = 16KB x2
#define SM_B(s) (32768 + (s) * 32768)      // 256 x 64 fp16 = 32KB x3
#define SM_W2   131072                     // 10KB
#define SM_PART 0                          // epilogue alias over A buffers (20KB)
#define SMEM_TOTAL (131072 + OUT * HID * 4)

// -------- helpers --------
__device__ __forceinline__ uint32_t smem_u32(const void* p) {
    uint32_t a;
    asm("{ .reg .u64 t; cvta.to.shared.u64 t, %1; cvt.u32.u64 %0, t; }" : "=r"(a) : "l"(p));
    return a;
}
__device__ __forceinline__ uint32_t swz(uint32_t off) {  // SW128
    return off ^ ((off >> 3) & 0x70);
}
__device__ __forceinline__ uint32_t pkh(__half a, __half b) {
    __half2 t(a, b);
    return *reinterpret_cast<uint32_t*>(&t);
}
__device__ __forceinline__ void ldm_x4(uint32_t& r0, uint32_t& r1, uint32_t& r2, uint32_t& r3,
                                       uint32_t addr) {
    asm volatile("ldmatrix.sync.aligned.m8n8.x4.shared.b16 {%0,%1,%2,%3}, [%4];"
                 : "=r"(r0), "=r"(r1), "=r"(r2), "=r"(r3) : "r"(addr));
}
__device__ __forceinline__ void mma16816(float* d, const uint32_t* a, const uint32_t* b) {
    asm volatile(
        "mma.sync.aligned.m16n8k16.row.col.f32.f16.f16.f32 "
        "{%0,%1,%2,%3}, {%4,%5,%6,%7}, {%8,%9}, {%0,%1,%2,%3};"
        : "+f"(d[0]), "+f"(d[1]), "+f"(d[2]), "+f"(d[3])
        : "r"(a[0]), "r"(a[1]), "r"(a[2]), "r"(a[3]), "r"(b[0]), "r"(b[1]));
}
__device__ __forceinline__ void cpa16(uint32_t dst, const void* src) {
    asm volatile("cp.async.cg.shared.global [%0], [%1], 16;" :: "r"(dst), "l"(src) : "memory");
}

// ---------------------------------------------------------------------------
__global__ void unpack_all(const int* __restrict__ w1p, const int* __restrict__ m1p,
                           const int* __restrict__ w2p, const int* __restrict__ m2p,
                           const float* __restrict__ a2) {
    int idx = blockIdx.x * 256 + threadIdx.x;
    if (idx < HID * KPAD) {
        int o = idx / KPAD, i = idx - o * KPAD;
        float v = 0.0f;
        if (i < IN1) {
            int sh = 7 - (i & 7);
            int wb = (w1p[o * W1B + (i >> 3)] >> sh) & 1;
            int mb = (m1p[o * W1B + (i >> 3)] >> sh) & 1;
            v = (2.0f * (float)wb - 1.0f) * (float)mb;
        }
        g_w1h[idx] = __float2half_rn(v);
    } else {
        int j = idx - HID * KPAD;
        if (j < OUT * HID) {
            int o = j / HID, i = j - o * HID;
            int sh = 7 - (i & 7);
            int wb = (w2p[o * W2B + (i >> 3)] >> sh) & 1;
            int mb = (m2p[o * W2B + (i >> 3)] >> sh) & 1;
            g_w2f[j] = (2.0f * (float)wb - 1.0f) * (float)mb * a2[0];
        }
    }
}

// ---------------------------------------------------------------------------
// Fused: D[128,256] = x_tile @ w1^T (fp16 mma, fp32 acc), then
// out = relu(alpha1*D) @ w2^T in-register.
// ---------------------------------------------------------------------------
__global__ void __launch_bounds__(NTHR, 1)
fused(const float* __restrict__ x, const float* __restrict__ alpha1,
      float* __restrict__ out) {
    extern __shared__ char smem[];
    const uint32_t sb = smem_u32(smem);
    const int tid = threadIdx.x, wid = tid >> 5, lane = tid & 31;
    const int wm = wid >> 2, wn = wid & 3;        // 2 x 4 warp grid, 64x64 tiles
    const int bm = blockIdx.x * BM;
    const float* __restrict__ xb = x + (size_t)bm * IN1;

    for (int i = tid; i < OUT * HID; i += NTHR)
        reinterpret_cast<float*>(smem + SM_W2)[i] = g_w2f[i];

    float acc[4][8][4];
    #pragma unroll
    for (int i = 0; i < 4; ++i)
        #pragma unroll
        for (int j = 0; j < 8; ++j)
            #pragma unroll
            for (int r = 0; r < 4; ++r) acc[i][j][r] = 0.0f;

    float4 sa[8];
    const int g = lane >> 3, lr = lane & 7;

    auto loadA = [&](int c) {
        const int kt = c * KC;
        #pragma unroll
        for (int it = 0; it < 8; ++it) {
            int idx = tid + it * NTHR;             // 0..2047 float4 slots
            int row = idx >> 4, f = idx & 15;
            int col = kt + f * 4;
            if (col < IN1)
                sa[it] = *reinterpret_cast<const float4*>(xb + (size_t)row * IN1 + col);
            else
                sa[it] = make_float4(0.f, 0.f, 0.f, 0.f);
        }
    };
    auto storeA = [&](int s) {
        #pragma unroll
        for (int it = 0; it < 8; ++it) {
            int idx = tid + it * NTHR;
            int row = idx >> 4, f = idx & 15;
            float4 v = sa[it];
            uint32_t sw = swz((uint32_t)(row * 128 + f * 8));
            *reinterpret_cast<uint2*>(smem + SM_A(s) + sw) =
                make_uint2(pkh(__float2half_rn(v.x), __float2half_rn(v.y)),
                           pkh(__float2half_rn(v.z), __float2half_rn(v.w)));
        }
    };
    auto issueB = [&](int c, int s) {
        const int kt = c * KC;
        #pragma unroll
        for (int it = 0; it < 8; ++it) {
            int idx = tid + it * NTHR;             // 0..2047 16B granules
            int n = idx >> 3, u = idx & 7;
            cpa16(sb + SM_B(s) + swz((uint32_t)(n * 128 + u * 16)),
                  g_w1h + (size_t)n * KPAD + kt + u * 8);
        }
        asm volatile("cp.async.commit_group;" ::: "memory");
    };
    auto compute = [&](int sa2, int s3) {
        #pragma unroll
        for (int ks = 0; ks < 4; ++ks) {
            uint32_t b[8][2];
            #pragma unroll
            for (int p = 0; p < 4; ++p) {
                int n  = wn * 64 + p * 16 + ((g & 2) ? 8 : 0) + lr;
                int kk = ks * 16 + ((g & 1) ? 8 : 0);
                ldm_x4(b[2 * p][0], b[2 * p][1], b[2 * p + 1][0], b[2 * p + 1][1],
                       sb + SM_B(s3) + swz((uint32_t)(n * 128 + kk * 2)));
            }
            uint32_t a[4][4];
            #pragma unroll
            for (int i = 0; i < 4; ++i) {
                int row = wm * 64 + i * 16 + ((g & 1) ? 8 : 0) + lr;
                int kk  = ks * 16 + ((g & 2) ? 8 : 0);
                ldm_x4(a[i][0], a[i][1], a[i][2], a[i][3],
                       sb + SM_A(sa2) + swz((uint32_t)(row * 128 + kk * 2)));
            }
            #pragma unroll
            for (int i = 0; i < 4; ++i)
                #pragma unroll
                for (int j = 0; j < 8; ++j) mma16816(acc[i][j], a[i], b[j]);
        }
    };

    // ---- prologue ----
    issueB(0, 0);                          // group 0
    issueB(1, 1);                          // group 1
    loadA(0); storeA(0);
    loadA(1);                              // regs hold chunk 1
    asm volatile("cp.async.wait_group 1;" ::: "memory");   // B0 ready
    __syncthreads();

    // ---- mainloop ----
    // invariant at iter c: A[c&1] + B[c%3] ready & visible; sa = x(c+1)
    for (int c = 0; c < NCHUNK; ++c) {
        if (c + 1 < NCHUNK) storeA((c + 1) & 1);           // STS only (own data)
        if (c + 2 < NCHUNK) {
            loadA(c + 2);                                  // LDG overlaps compute
            issueB(c + 2, (c + 2) % 3);                    // into buffer freed at c-1
        }
        compute(c & 1, c % 3);
        if (c + 1 < NCHUNK) {
            if (c + 2 < NCHUNK)
                asm volatile("cp.async.wait_group 1;" ::: "memory");
            else
                asm volatile("cp.async.wait_group 0;" ::: "memory");
            __syncthreads();
        }
    }

    // ---- epilogue: out = relu(a1*acc) @ w2^T ----
    __syncthreads();                        // before aliasing A smem
    const float a1v = alpha1[0];
    #pragma unroll
    for (int i = 0; i < 4; ++i)
        #pragma unroll
        for (int j = 0; j < 8; ++j)
            #pragma unroll
            for (int r = 0; r < 4; ++r)
                acc[i][j][r] = fmaxf(a1v * acc[i][j][r], 0.0f);

    const float* w2s = reinterpret_cast<const float*>(smem + SM_W2);
    float* part = reinterpret_cast<float*>(smem + SM_PART);
    const int q = lane & 3, gq = lane >> 2;

    #pragma unroll
    for (int o = 0; o < OUT; ++o) {
        float w2v[8][2];
        #pragma unroll
        for (int j = 0; j < 8; ++j) {
            w2v[j][0] = w2s[o * HID + wn * 64 + j * 8 + q * 2];
            w2v[j][1] = w2s[o * HID + wn * 64 + j * 8 + q * 2 + 1];
        }
        #pragma unroll
        for (int i = 0; i < 4; ++i)
            #pragma unroll
            for (int h2 = 0; h2 < 2; ++h2) {
                float s = 0.0f;
                #pragma unroll
                for (int j = 0; j < 8; ++j)
                    s += acc[i][j][h2 * 2] * w2v[j][0] + acc[i][j][h2 * 2 + 1] * w2v[j][1];
                s += __shfl_xor_sync(0xffffffffu, s, 1);
                s += __shfl_xor_sync(0xffffffffu, s, 2);
                if (q == 0) {
                    int row = wm * 64 + i * 16 + h2 * 8 + gq;
                    part[wn * (BM * OUT) + row * OUT + o] = s;
                }
            }
    }
    __syncthreads();

    for (int idx = tid; idx < BM * OUT; idx += NTHR) {
        float v = part[idx] + part[BM * OUT + idx] +
                  part[2 * BM * OUT + idx] + part[3 * BM * OUT + idx];
        out[(size_t)bm * OUT + idx] = v;
    }
}

// ---------------------------------------------------------------------------
extern "C" void kernel_launch(void* const* d_in, const int* in_sizes, int n_in,
                              void* d_out, int out_size) {
    const float* x   = (const float*)d_in[0];
    const int*   w1p = (const int*)d_in[1];
    const int*   m1p = (const int*)d_in[2];
    const float* a1  = (const float*)d_in[3];
    const int*   w2p = (const int*)d_in[4];
    const int*   m2p = (const int*)d_in[5];
    const float* a2  = (const float*)d_in[6];
    float* out = (float*)d_out;

    cudaFuncSetAttribute(fused, cudaFuncAttributeMaxDynamicSharedMemorySize, SMEM_TOTAL);

    int total = HID * KPAD + OUT * HID;
    unpack_all<<<(total + 255) / 256, 256>>>(w1p, m1p, w2p, m2p, a2);
    fused<<<BATCH / BM, NTHR, SMEM_TOTAL>>>(x, a1, out);
}